// round 1
// baseline (speedup 1.0000x reference)
#include <cuda_runtime.h>
#include <math.h>

#define Bn 8
#define Nn 10000
#define Hh 64
#define Ll 4
#define Rr 3
#define Ee 200000
#define FPn 2048
#define ROWS (Nn*Bn)            /* 80000 rows of 64 floats; row m = n*8+b  */
#define LN_EPS 1e-3f

// ---------------- device scratch (static, no runtime allocation) ----------------
__device__ float g_x0[ROWS*Hh];            // ping
__device__ float g_x1[ROWS*Hh];            // pong
__device__ float g_agg[Rr*ROWS*Hh];        // per-relation aggregation (x-space)
__device__ float g_film[Bn*2*Hh];          // [b][0:64]=1+tanh(gamma), [64:128]=beta
__device__ int   g_rowptr[Rr*(Nn+1)];      // CSR row pointers (by dst)
__device__ int   g_cnt[Rr*Nn];             // degree, then fill cursor
__device__ int   g_esrc[Rr*Ee];            // CSR src ids
__device__ float g_ew[Rr*Ee];              // CSR edge weights

// ---------------- FiLM: gamma/beta per batch --------------------------------
__global__ void film_kernel(const float* __restrict__ fp,
                            const float* __restrict__ W1, const float* __restrict__ b1,
                            const float* __restrict__ W2, const float* __restrict__ b2)
{
    __shared__ float hid[Bn*Hh];
    int t = threadIdx.x;                   // 512 threads
    int b = t >> 6, h = t & 63;
    float acc = b1[h];
    const float* fpb = fp + b*FPn;
    #pragma unroll 4
    for (int k = 0; k < FPn; k++) acc += fpb[k] * W1[k*Hh + h];
    hid[t] = fmaxf(acc, 0.f);
    __syncthreads();
    for (int o = t; o < Bn*128; o += 512) {
        int bb = o >> 7, j = o & 127;
        float a = b2[j];
        const float* hb = hid + bb*Hh;
        #pragma unroll
        for (int k = 0; k < Hh; k++) a += hb[k] * W2[k*128 + j];
        if (j < 64) g_film[bb*128 + j] = 1.f + tanhf(a);
        else        g_film[bb*128 + j] = a;
    }
}

// ---------------- initial node features -------------------------------------
__global__ void init_x_kernel(const float* __restrict__ ctl, const float* __restrict__ drug,
                              const float* __restrict__ W_se, const float* __restrict__ b_se,
                              const float* __restrict__ cell_emb, const int* __restrict__ cell_idx)
{
    int i = blockIdx.x*blockDim.x + threadIdx.x;
    if (i >= ROWS*Hh) return;
    int h = i & 63;
    int m = i >> 6;
    int b = m & 7;
    int n = m >> 3;
    float w = W_se[h], bs = b_se[h];
    float v1 = ctl[b*Nn + n], v2 = drug[b*Nn + n];
    float xv = fmaxf(fmaf(v1, w, bs), 0.f) + fmaxf(fmaf(v2, w, bs), 0.f);
    xv += cell_emb[cell_idx[b]*Hh + h];
    xv = fmaf(xv, g_film[b*128 + h], g_film[b*128 + 64 + h]);
    g_x0[i] = xv;
}

// ---------------- CSR build ---------------------------------------------------
__global__ void zero_deg_kernel()
{
    int i = blockIdx.x*blockDim.x + threadIdx.x;
    if (i < Rr*Nn) g_cnt[i] = 0;
}

__global__ void hist_kernel(const int* __restrict__ ei)
{
    int i = blockIdx.x*blockDim.x + threadIdx.x;
    if (i >= Rr*Ee) return;
    int r = i / Ee, e = i - r*Ee;
    int dst = ei[(r*2 + 1)*Ee + e];
    atomicAdd(&g_cnt[r*Nn + dst], 1);
}

__global__ void scan_kernel()   // grid = Rr blocks x 1024 threads
{
    int r = blockIdx.x, t = threadIdx.x;
    __shared__ int s[1024];
    int carry = 0;
    if (t == 0) g_rowptr[r*(Nn+1)] = 0;
    for (int base = 0; base < Nn; base += 1024) {
        int idx = base + t;
        int v = (idx < Nn) ? g_cnt[r*Nn + idx] : 0;
        s[t] = v;
        __syncthreads();
        for (int off = 1; off < 1024; off <<= 1) {
            int add = (t >= off) ? s[t - off] : 0;
            __syncthreads();
            s[t] += add;
            __syncthreads();
        }
        if (idx < Nn) {
            g_rowptr[r*(Nn+1) + idx + 1] = carry + s[t];
            g_cnt[r*Nn + idx] = carry + s[t] - v;   // exclusive prefix = fill cursor
        }
        carry += s[1023];
        __syncthreads();
    }
}

__global__ void fill_kernel(const int* __restrict__ ei, const float* __restrict__ ew)
{
    int i = blockIdx.x*blockDim.x + threadIdx.x;
    if (i >= Rr*Ee) return;
    int r = i / Ee, e = i - r*Ee;
    int src = ei[(r*2 + 0)*Ee + e];
    int dst = ei[(r*2 + 1)*Ee + e];
    int pos = atomicAdd(&g_cnt[r*Nn + dst], 1);
    g_esrc[r*Ee + pos] = src;
    g_ew  [r*Ee + pos] = ew[r*Ee + e];
}

// ---------------- gather: agg_r[dst] = sum_e w_e * x[src_e] -------------------
__global__ void gather_kernel(int layer)  // grid (Nn, Rr) x 128 threads
{
    const float* x = (layer & 1) ? g_x1 : g_x0;
    int dst = blockIdx.x, r = blockIdx.y;
    int t = threadIdx.x;                       // one float4 of the 512-float node row
    int start = g_rowptr[r*(Nn+1) + dst];
    int end   = g_rowptr[r*(Nn+1) + dst + 1];
    const float4* __restrict__ x4 = (const float4*)x;
    const int*   __restrict__ es = g_esrc + r*Ee;
    const float* __restrict__ ws = g_ew   + r*Ee;
    float4 acc = make_float4(0.f, 0.f, 0.f, 0.f);
    int j = start;
    // 2-deep software pipeline for MLP on the src->x dependent chain
    for (; j + 1 < end; j += 2) {
        int s0 = es[j],   s1 = es[j+1];
        float w0 = ws[j], w1 = ws[j+1];
        float4 v0 = x4[s0*128 + t];
        float4 v1 = x4[s1*128 + t];
        acc.x = fmaf(w0, v0.x, acc.x); acc.y = fmaf(w0, v0.y, acc.y);
        acc.z = fmaf(w0, v0.z, acc.z); acc.w = fmaf(w0, v0.w, acc.w);
        acc.x = fmaf(w1, v1.x, acc.x); acc.y = fmaf(w1, v1.y, acc.y);
        acc.z = fmaf(w1, v1.z, acc.z); acc.w = fmaf(w1, v1.w, acc.w);
    }
    if (j < end) {
        int s0 = es[j]; float w0 = ws[j];
        float4 v0 = x4[s0*128 + t];
        acc.x = fmaf(w0, v0.x, acc.x); acc.y = fmaf(w0, v0.y, acc.y);
        acc.z = fmaf(w0, v0.z, acc.z); acc.w = fmaf(w0, v0.w, acc.w);
    }
    ((float4*)g_agg)[r*(ROWS*Hh/4) + dst*128 + t] = acc;
}

// ---------------- fused GEMM (K=256) + LayerNorm + ReLU ----------------------
__global__ __launch_bounds__(256)
void gemm_ln_kernel(const float* __restrict__ Wself, const float* __restrict__ Wrel,
                    const float* __restrict__ ln_g,  const float* __restrict__ ln_b,
                    int layer)
{
    const float* xin  = (layer & 1) ? g_x1 : g_x0;
    float*       xout = (layer & 1) ? g_x0 : g_x1;

    __shared__ float sIn[64][68];   // [k][row] (transposed, padded: 272B rows keep float4 alignment)
    __shared__ float sW[64*64];     // [k][col]

    int tid = threadIdx.x;
    int row0 = blockIdx.x * 64;
    int tc = tid & 15;              // col group: cols 4*tc..4*tc+3
    int tr = tid >> 4;              // row group: rows 4*tr..4*tr+3

    float acc[4][4];
    #pragma unroll
    for (int i = 0; i < 4; i++)
        #pragma unroll
        for (int jx = 0; jx < 4; jx++) acc[i][jx] = 0.f;

    for (int s = 0; s < 4; s++) {
        const float* src = (s == 0) ? (xin + row0*Hh)
                                    : (g_agg + (s-1)*(ROWS*Hh) + row0*Hh);
        const float* W   = (s == 0) ? (Wself + layer*Hh*Hh)
                                    : (Wrel + (layer*Rr + (s-1))*Hh*Hh);
        for (int i = tid; i < 4096; i += 256) sW[i] = W[i];
        for (int i = tid; i < 4096; i += 256) {
            int rr = i >> 6, kk = i & 63;
            sIn[kk][rr] = src[i];
        }
        __syncthreads();
        #pragma unroll 16
        for (int k = 0; k < 64; k++) {
            float4 a = *(const float4*)&sIn[k][tr*4];
            float4 w = *(const float4*)&sW[k*64 + tc*4];
            acc[0][0] = fmaf(a.x, w.x, acc[0][0]); acc[0][1] = fmaf(a.x, w.y, acc[0][1]);
            acc[0][2] = fmaf(a.x, w.z, acc[0][2]); acc[0][3] = fmaf(a.x, w.w, acc[0][3]);
            acc[1][0] = fmaf(a.y, w.x, acc[1][0]); acc[1][1] = fmaf(a.y, w.y, acc[1][1]);
            acc[1][2] = fmaf(a.y, w.z, acc[1][2]); acc[1][3] = fmaf(a.y, w.w, acc[1][3]);
            acc[2][0] = fmaf(a.z, w.x, acc[2][0]); acc[2][1] = fmaf(a.z, w.y, acc[2][1]);
            acc[2][2] = fmaf(a.z, w.z, acc[2][2]); acc[2][3] = fmaf(a.z, w.w, acc[2][3]);
            acc[3][0] = fmaf(a.w, w.x, acc[3][0]); acc[3][1] = fmaf(a.w, w.y, acc[3][1]);
            acc[3][2] = fmaf(a.w, w.z, acc[3][2]); acc[3][3] = fmaf(a.w, w.w, acc[3][3]);
        }
        __syncthreads();
    }

    // LayerNorm over the 64 cols of each row (cols live in 16 lanes x 4 regs)
    float4 gg = *(const float4*)&ln_g[layer*64 + tc*4];
    float4 bb = *(const float4*)&ln_b[layer*64 + tc*4];
    #pragma unroll
    for (int rr = 0; rr < 4; rr++) {
        float s1 = acc[rr][0] + acc[rr][1] + acc[rr][2] + acc[rr][3];
        float s2 = acc[rr][0]*acc[rr][0] + acc[rr][1]*acc[rr][1]
                 + acc[rr][2]*acc[rr][2] + acc[rr][3]*acc[rr][3];
        #pragma unroll
        for (int off = 8; off >= 1; off >>= 1) {
            s1 += __shfl_xor_sync(0xffffffffu, s1, off, 16);
            s2 += __shfl_xor_sync(0xffffffffu, s2, off, 16);
        }
        float mu  = s1 * (1.f/64.f);
        float var = s2 * (1.f/64.f) - mu*mu;
        float inv = rsqrtf(var + LN_EPS);
        float4 o;
        o.x = fmaxf(fmaf((acc[rr][0]-mu)*inv, gg.x, bb.x), 0.f);
        o.y = fmaxf(fmaf((acc[rr][1]-mu)*inv, gg.y, bb.y), 0.f);
        o.z = fmaxf(fmaf((acc[rr][2]-mu)*inv, gg.z, bb.z), 0.f);
        o.w = fmaxf(fmaf((acc[rr][3]-mu)*inv, gg.w, bb.w), 0.f);
        *(float4*)&xout[(row0 + tr*4 + rr)*64 + tc*4] = o;
    }
}

// ---------------- output projection [B,N] ------------------------------------
__global__ void out_kernel(const float* __restrict__ W_out, const float* __restrict__ b_out,
                           float* __restrict__ out)
{
    int gid  = blockIdx.x*blockDim.x + threadIdx.x;
    int warp = gid >> 5;
    int lane = threadIdx.x & 31;
    if (warp >= ROWS) return;
    const float* xr = g_x0 + warp*64;     // after 4 layers x lives in g_x0
    float v = xr[lane] * W_out[lane] + xr[32 + lane] * W_out[32 + lane];
    #pragma unroll
    for (int off = 16; off >= 1; off >>= 1)
        v += __shfl_xor_sync(0xffffffffu, v, off);
    if (lane == 0) {
        int b = warp & 7, n = warp >> 3;
        out[b*Nn + n] = v + b_out[0];
    }
}

// ---------------- launch ------------------------------------------------------
extern "C" void kernel_launch(void* const* d_in, const int* in_sizes, int n_in,
                              void* d_out, int out_size)
{
    const float* ctl      = (const float*)d_in[0];
    const float* drug     = (const float*)d_in[1];
    const float* fp       = (const float*)d_in[2];
    const float* ew       = (const float*)d_in[3];
    const int*   cell_idx = (const int*)  d_in[4];
    const int*   ei       = (const int*)  d_in[5];
    const float* W_se     = (const float*)d_in[6];
    const float* b_se     = (const float*)d_in[7];
    const float* cell_emb = (const float*)d_in[8];
    const float* W_f1     = (const float*)d_in[9];
    const float* b_f1     = (const float*)d_in[10];
    const float* W_f2     = (const float*)d_in[11];
    const float* b_f2     = (const float*)d_in[12];
    const float* Wself    = (const float*)d_in[13];
    const float* Wrel     = (const float*)d_in[14];
    const float* ln_g     = (const float*)d_in[15];
    const float* ln_b     = (const float*)d_in[16];
    const float* W_out    = (const float*)d_in[17];
    const float* b_out    = (const float*)d_in[18];
    float* out = (float*)d_out;

    film_kernel<<<1, 512>>>(fp, W_f1, b_f1, W_f2, b_f2);
    init_x_kernel<<<(ROWS*Hh + 255)/256, 256>>>(ctl, drug, W_se, b_se, cell_emb, cell_idx);

    zero_deg_kernel<<<(Rr*Nn + 255)/256, 256>>>();
    hist_kernel<<<(Rr*Ee + 255)/256, 256>>>(ei);
    scan_kernel<<<Rr, 1024>>>();
    fill_kernel<<<(Rr*Ee + 255)/256, 256>>>(ei, ew);

    for (int l = 0; l < Ll; l++) {
        gather_kernel<<<dim3(Nn, Rr), 128>>>(l);
        gemm_ln_kernel<<<ROWS/64, 256>>>(Wself, Wrel, ln_g, ln_b, l);
    }

    out_kernel<<<(ROWS*32 + 255)/256, 256>>>(W_out, b_out, out);
}